// round 1
// baseline (speedup 1.0000x reference)
#include <cuda_runtime.h>
#include <cuda_bf16.h>

#define NN   50000
#define EE   800000
#define KIN  256
#define FOUT 128
#define NEG_ATT 0.2f
#define NEG_ACT 0.01f
#define BN_EPS  1e-5f

// Scratch (static device arrays — no allocations allowed)
__device__ __align__(16) float g_h[(size_t)NN * FOUT];   // projected features
__device__ __align__(16) float g_s[NN * 4];              // a_src per node/head
__device__ __align__(16) float g_d[NN * 4];              // a_dst per node/head
__device__ __align__(16) float g_den[NN * 4];            // softmax denominator
__device__ __align__(16) float g_stats[256];             // col sum[128], sumsq[128]

// ---------------------------------------------------------------------------
// Kernel 1: h = x @ W^T   (64x128 block tile, BK=32, 4x8 register tile)
// ---------------------------------------------------------------------------
__global__ __launch_bounds__(256) void gemm_k(const float* __restrict__ x,
                                              const float* __restrict__ W) {
    __shared__ float As[32][68];    // [k][m], padded
    __shared__ float Bs[32][128];   // [k][n]
    const int row0 = blockIdx.x * 64;
    const int tid  = threadIdx.x;
    const int tr   = tid >> 4;      // 0..15 -> 4 rows each
    const int tc   = tid & 15;      // 0..15 -> 8 cols each

    float acc[4][8];
#pragma unroll
    for (int i = 0; i < 4; i++)
#pragma unroll
        for (int j = 0; j < 8; j++) acc[i][j] = 0.f;

    for (int k0 = 0; k0 < KIN; k0 += 32) {
        // Load A tile: 64x32 floats = 512 float4, 2 per thread (transposed store)
#pragma unroll
        for (int i = 0; i < 2; i++) {
            int f = tid * 2 + i;
            int r = f >> 3, kk = (f & 7) << 2;
            int gr = row0 + r;
            float4 v = make_float4(0.f, 0.f, 0.f, 0.f);
            if (gr < NN) v = *(const float4*)(x + (size_t)gr * KIN + k0 + kk);
            As[kk + 0][r] = v.x; As[kk + 1][r] = v.y;
            As[kk + 2][r] = v.z; As[kk + 3][r] = v.w;
        }
        // Load B tile: W[128][256] chunk -> Bs[k][j]; 1024 float4, 4 per thread
#pragma unroll
        for (int i = 0; i < 4; i++) {
            int f = tid * 4 + i;
            int j = f >> 3, kk = (f & 7) << 2;
            float4 v = *(const float4*)(W + (size_t)j * KIN + k0 + kk);
            Bs[kk + 0][j] = v.x; Bs[kk + 1][j] = v.y;
            Bs[kk + 2][j] = v.z; Bs[kk + 3][j] = v.w;
        }
        __syncthreads();
#pragma unroll
        for (int k = 0; k < 32; k++) {
            float4 a  = *(const float4*)&As[k][tr * 4];
            float4 b0 = *(const float4*)&Bs[k][tc * 8];
            float4 b1 = *(const float4*)&Bs[k][tc * 8 + 4];
            float av[4] = {a.x, a.y, a.z, a.w};
            float bv[8] = {b0.x, b0.y, b0.z, b0.w, b1.x, b1.y, b1.z, b1.w};
#pragma unroll
            for (int i = 0; i < 4; i++)
#pragma unroll
                for (int j = 0; j < 8; j++) acc[i][j] += av[i] * bv[j];
        }
        __syncthreads();
    }
#pragma unroll
    for (int i = 0; i < 4; i++) {
        int gr = row0 + tr * 4 + i;
        if (gr < NN) {
            float* p = g_h + (size_t)gr * FOUT + tc * 8;
            *(float4*)(p)     = make_float4(acc[i][0], acc[i][1], acc[i][2], acc[i][3]);
            *(float4*)(p + 4) = make_float4(acc[i][4], acc[i][5], acc[i][6], acc[i][7]);
        }
    }
}

// ---------------------------------------------------------------------------
// Kernel 2: per-node attention scores + self-loop init of accumulators.
// One warp per node. lane -> head = lane>>3, sub = lane&7 (4 channels each).
// out[i] = w_self * h[i];  den[i] = w_self;  also stores a_s, a_d.
// ---------------------------------------------------------------------------
__global__ __launch_bounds__(256) void node_init_k(const float* __restrict__ att_src,
                                                   const float* __restrict__ att_dst,
                                                   float* __restrict__ out) {
    int warp = (blockIdx.x * blockDim.x + threadIdx.x) >> 5;
    int lane = threadIdx.x & 31;
    if (warp >= NN) return;
    int head = lane >> 3, sub = lane & 7;

    float4 hv  = *(const float4*)(g_h + (size_t)warp * FOUT + lane * 4);
    float4 as4 = *(const float4*)(att_src + head * 32 + sub * 4);
    float4 ad4 = *(const float4*)(att_dst + head * 32 + sub * 4);
    float ps = hv.x * as4.x + hv.y * as4.y + hv.z * as4.z + hv.w * as4.w;
    float pd = hv.x * ad4.x + hv.y * ad4.y + hv.z * ad4.z + hv.w * ad4.w;
    // xor-reduce within the 8-lane head group (all lanes end with full sum)
#pragma unroll
    for (int o = 4; o; o >>= 1) {
        ps += __shfl_xor_sync(0xFFFFFFFFu, ps, o);
        pd += __shfl_xor_sync(0xFFFFFFFFu, pd, o);
    }
    float e = ps + pd;
    e = e < 0.f ? NEG_ATT * e : e;
    float w = __expf(e);

    *(float4*)(out + (size_t)warp * FOUT + lane * 4) =
        make_float4(w * hv.x, w * hv.y, w * hv.z, w * hv.w);
    if (sub == 0) {
        g_s[warp * 4 + head]   = ps;
        g_d[warp * 4 + head]   = pd;
        g_den[warp * 4 + head] = w;
    }
}

// ---------------------------------------------------------------------------
// Kernel 3: edge scatter. One warp per edge.
// w = exp(leaky_relu(a_s[src] + a_d[dst])); atomically accumulate
// denominator and w * h[src] into out[dst] via vectorized RED.128.
// ---------------------------------------------------------------------------
__global__ __launch_bounds__(256) void edge_k(const int* __restrict__ ei,
                                              float* __restrict__ out) {
    int warp = (int)((blockIdx.x * (unsigned)blockDim.x + threadIdx.x) >> 5);
    int lane = threadIdx.x & 31;
    if (warp >= EE) return;
    int src = ei[warp];
    int dst = ei[EE + warp];
    int head = lane >> 3;

    float e = g_s[src * 4 + head] + g_d[dst * 4 + head];
    e = e < 0.f ? NEG_ATT * e : e;
    float w = __expf(e);
    if ((lane & 7) == 0)
        atomicAdd(&g_den[dst * 4 + head], w);

    float4 hv = *(const float4*)(g_h + (size_t)src * FOUT + lane * 4);
    float* p = out + (size_t)dst * FOUT + lane * 4;
    asm volatile("red.global.add.v4.f32 [%0], {%1,%2,%3,%4};"
                 :: "l"(p), "f"(w * hv.x), "f"(w * hv.y),
                    "f"(w * hv.z), "f"(w * hv.w)
                 : "memory");
}

// ---------------------------------------------------------------------------
// Kernel 4a: zero the BN stats accumulators
// ---------------------------------------------------------------------------
__global__ void zero_stats_k() { g_stats[threadIdx.x] = 0.f; }

// ---------------------------------------------------------------------------
// Kernel 4b: column-wise sum / sumsq of y = out/den + bias.
// blockDim = 128 (thread = column), each block handles a row stripe.
// ---------------------------------------------------------------------------
__global__ __launch_bounds__(128) void stats_k(const float* __restrict__ out,
                                               const float* __restrict__ bias) {
    int c = threadIdx.x;
    int rpb = (NN + gridDim.x - 1) / gridDim.x;
    int r0 = blockIdx.x * rpb;
    int r1 = min(r0 + rpb, NN);
    float b = bias[c];
    int hsel = c >> 5;
    float s = 0.f, ss = 0.f;
    for (int r = r0; r < r1; r++) {
        float y = out[(size_t)r * FOUT + c] / g_den[r * 4 + hsel] + b;
        s += y; ss += y * y;
    }
    atomicAdd(&g_stats[c], s);
    atomicAdd(&g_stats[128 + c], ss);
}

// ---------------------------------------------------------------------------
// Kernel 5: finalize — normalize, BN affine, LeakyReLU(0.01), in place.
// ---------------------------------------------------------------------------
__global__ __launch_bounds__(256) void final_k(float* __restrict__ out,
                                               const float* __restrict__ bias,
                                               const float* __restrict__ gamma,
                                               const float* __restrict__ beta) {
    size_t idx = (size_t)blockIdx.x * blockDim.x + threadIdx.x;
    if (idx >= (size_t)NN * FOUT) return;
    int c = (int)(idx & 127);
    size_t r = idx >> 7;
    float y = out[idx] / g_den[r * 4 + (c >> 5)] + bias[c];
    const float invN = 1.0f / NN;
    float mu  = g_stats[c] * invN;
    float var = g_stats[128 + c] * invN - mu * mu;
    float v = (y - mu) * rsqrtf(var + BN_EPS) * gamma[c] + beta[c];
    out[idx] = v < 0.f ? NEG_ACT * v : v;
}

// ---------------------------------------------------------------------------
extern "C" void kernel_launch(void* const* d_in, const int* in_sizes, int n_in,
                              void* d_out, int out_size) {
    const float* x       = (const float*)d_in[0];
    const int*   ei      = (const int*)  d_in[1];
    const float* W       = (const float*)d_in[2];
    const float* att_src = (const float*)d_in[3];
    const float* att_dst = (const float*)d_in[4];
    const float* bias    = (const float*)d_in[5];
    const float* gamma   = (const float*)d_in[6];
    const float* beta    = (const float*)d_in[7];
    float* out = (float*)d_out;

    gemm_k<<<(NN + 63) / 64, 256>>>(x, W);
    node_init_k<<<(NN * 32 + 255) / 256, 256>>>(att_src, att_dst, out);
    edge_k<<<(EE * 32 + 255) / 256, 256>>>(ei, out);
    zero_stats_k<<<1, 256>>>();
    stats_k<<<512, 128>>>(out, bias);
    final_k<<<(int)(((size_t)NN * FOUT + 255) / 256), 256>>>(out, bias, gamma, beta);
}